// round 16
// baseline (speedup 1.0000x reference)
#include <cuda_runtime.h>
#include <cuda_bf16.h>
#include <cstdint>

#define Bq 4
#define NF 5
#define HSq 512
#define Sq 1024
#define NPAIR 255   // (HSq-2)/2 row pairs

#define XF(ff,jj,ii) xb[((size_t)(ff)*HSq + (jj))*Sq + (ii)]

// Boundary point: the reference's 12 perimeter cases for one (j,i).
__device__ __forceinline__ void bpoint(
    const float* __restrict__ xb, const float* __restrict__ poles,
    const float* __restrict__ we,   const float* __restrict__ wcn,
    const float* __restrict__ wne,  const float* __restrict__ wnne,
    const float* __restrict__ wnw,  const float* __restrict__ wnww,
    const float* __restrict__ wwe,  const float* __restrict__ wsw,
    const float* __restrict__ wsse, const float* __restrict__ wse,
    const float* __restrict__ wcs,
    int b, int f, int pf, int nf2, int j, int i,
    float& c0, float& c1, float& c2, float& c3)
{
    if (j == 0) {
        float ctr = XF(f, 0, i);
        if (i == 0) {
            c0 = (XF(pf, HSq - 1, HSq - 1) - ctr) * wcs[0];
            c1 = (XF(f, 1, 1) - ctr) * wcs[1];
            c2 = (XF(pf, HSq - 1, HSq) - ctr) * wcs[2] + (XF(f, 0, 1) - ctr) * wcs[3];
            c3 = (XF(f, 1, 0) - ctr) * wcs[4];
        } else if (i <= HSq - 1) {
            int k = i - 1; const int W = HSq - 1;
            c0 = (XF(pf, HSq - 1, HSq + k) - ctr) * we[k];
            c1 = (XF(f, 1, i + 1) - ctr) * we[W + k];
            c2 = (XF(pf, HSq - 1, HSq + 1 + k) - ctr) * we[2 * W + k]
               + (XF(f, 0, i + 1) - ctr) * we[3 * W + k];
            c3 = (XF(f, 0, i - 1) - ctr) * we[4 * W + k]
               + (XF(f, 1, i) - ctr) * we[5 * W + k];
        } else if (i == HSq) {
            c0 = (XF(pf, HSq - 1, Sq - 1) - ctr) * wcn[0];
            c1 = (XF(f, 1, HSq + 1) - ctr) * wcn[1];
            c2 = (XF(f, 0, HSq + 1) - ctr) * wcn[2];
            c3 = (XF(f, 0, HSq - 1) - ctr) * wcn[3] + (XF(f, 1, HSq) - ctr) * wcn[4];
        } else if (i <= Sq - 2) {
            int k = i - (HSq + 1); const int W = HSq - 2;
            c0 = (XF(pf, HSq - 2 - k, Sq - 1) - ctr) * wne[k]
               + (XF(pf, HSq - 1 - k, Sq - 1) - ctr) * wne[W + k];
            c1 = (XF(f, 1, i + 1) - ctr) * wne[2 * W + k]
               + (XF(f, 1, i) - ctr) * wne[3 * W + k];
            c2 = (XF(f, 0, i + 1) - ctr) * wne[4 * W + k];
            c3 = (XF(f, 0, i - 1) - ctr) * wne[5 * W + k];
        } else {
            c0 = (XF(pf, 0, Sq - 1) - ctr) * wnne[0] + (XF(pf, 1, Sq - 1) - ctr) * wnne[1];
            c1 = (XF(nf2, 0, Sq - 1) - ctr) * wnne[2] + (XF(f, 1, Sq - 1) - ctr) * wnne[3];
            c2 = (poles[b * 2 + 1] - ctr) * wnne[4];
            c3 = (XF(f, 0, Sq - 2) - ctr) * wnne[5];
        }
    } else if (j == HSq - 1) {
        float ctr = XF(f, HSq - 1, i);
        if (i == 0) {
            c0 = (XF(pf, HSq - 1, 0) - ctr) * wsse[0];
            c1 = (XF(nf2, HSq - 1, 0) - ctr) * wsse[1];
            c2 = (XF(f, HSq - 2, 0) - ctr) * wsse[2] + (XF(f, HSq - 1, 1) - ctr) * wsse[3];
            c3 = (poles[b * 2 + 0] - ctr) * wsse[4];
        } else if (i <= HSq - 1) {
            int k = i - 1; const int W = HSq - 1;
            c0 = (XF(f, HSq - 2, i - 1) - ctr) * wsw[k];
            c1 = (XF(nf2, HSq - 2 - k, 0) - ctr) * wsw[W + k];
            c2 = (XF(f, HSq - 2, i) - ctr) * wsw[2 * W + k]
               + (XF(f, HSq - 1, i + 1) - ctr) * wsw[3 * W + k];
            c3 = (XF(f, HSq - 1, i - 1) - ctr) * wsw[4 * W + k]
               + (XF(nf2, HSq - 1 - k, 0) - ctr) * wsw[5 * W + k];
        } else if (i <= Sq - 2) {
            int k = i - HSq; const int W = HSq - 1;
            c0 = (XF(f, HSq - 2, i - 1) - ctr) * wwe[k];
            c1 = (XF(nf2, 0, 1 + k) - ctr) * wwe[W + k];
            c2 = (XF(f, HSq - 2, i) - ctr) * wwe[2 * W + k]
               + (XF(f, HSq - 1, i + 1) - ctr) * wwe[3 * W + k];
            c3 = (XF(f, HSq - 1, i - 1) - ctr) * wwe[4 * W + k]
               + (XF(nf2, 0, k) - ctr) * wwe[5 * W + k];
        } else {
            c0 = (XF(f, HSq - 2, Sq - 2) - ctr) * wnww[0];
            c1 = (XF(nf2, 0, HSq) - ctr) * wnww[1];
            c2 = (XF(f, HSq - 2, Sq - 1) - ctr) * wnww[2]
               + (XF(nf2, 0, HSq + 1) - ctr) * wnww[3];
            c3 = (XF(f, HSq - 1, Sq - 2) - ctr) * wnww[4]
               + (XF(nf2, 0, HSq - 1) - ctr) * wnww[5];
        }
    } else if (i == 0) {
        int k = j - 1; const int W = HSq - 2;
        float ctr = XF(f, j, 0);
        c0 = (XF(pf, HSq - 1, HSq - 1 - k) - ctr) * wse[k]
           + (XF(pf, HSq - 1, HSq - 2 - k) - ctr) * wse[W + k];
        c1 = (XF(f, j, 1) - ctr) * wse[2 * W + k]
           + (XF(f, j + 1, 1) - ctr) * wse[3 * W + k];
        c2 = (XF(f, j - 1, 0) - ctr) * wse[4 * W + k];
        c3 = (XF(f, j + 1, 0) - ctr) * wse[5 * W + k];
    } else {
        int k = j - 1; const int W = HSq - 2;
        float ctr = XF(f, j, Sq - 1);
        c0 = (XF(f, j - 1, Sq - 2) - ctr) * wnw[k];
        c1 = (XF(nf2, 0, Sq - 2 - k) - ctr) * wnw[W + k];
        c2 = (XF(f, j - 1, Sq - 1) - ctr) * wnw[2 * W + k]
           + (XF(nf2, 0, Sq - 1 - k) - ctr) * wnw[3 * W + k];
        c3 = (XF(f, j, Sq - 2) - ctr) * wnw[4 * W + k]
           + (XF(f, j + 1, Sq - 1) - ctr) * wnw[5 * W + k];
    }
}

// Inner scalar point (global-memory path, edge threads only)
__device__ __forceinline__ void ipoint(
    const float* __restrict__ xp, const float* __restrict__ wi,
    int j, int i, float& c0, float& c1, float& c2, float& c3)
{
    const int WP = (HSq - 2) * (Sq - 2);
    int k = (j - 1) * (Sq - 2) + (i - 1);
    float ctr = xp[(size_t)j * Sq + i];
    c0 = (xp[(size_t)(j - 1) * Sq + i - 1] - ctr) * wi[k];
    c1 = (xp[(size_t)(j + 1) * Sq + i + 1] - ctr) * wi[WP + k];
    c2 = (xp[(size_t)(j - 1) * Sq + i] - ctr) * wi[2 * WP + k]
       + (xp[(size_t)j * Sq + i + 1] - ctr) * wi[3 * WP + k];
    c3 = (xp[(size_t)j * Sq + i - 1] - ctr) * wi[4 * WP + k]
       + (xp[(size_t)(j + 1) * Sq + i] - ctr) * wi[5 * WP + k];
}

__global__ void __launch_bounds__(128) fused_kernel(
    const float* __restrict__ x,
    const float* __restrict__ poles,
    const float* __restrict__ wi,
    const float* __restrict__ we,   const float* __restrict__ wcn,
    const float* __restrict__ wne,  const float* __restrict__ wnne,
    const float* __restrict__ wnw,  const float* __restrict__ wnww,
    const float* __restrict__ wwe,  const float* __restrict__ wsw,
    const float* __restrict__ wsse, const float* __restrict__ wse,
    const float* __restrict__ wcs,
    float* __restrict__ out)
{
    const size_t FP  = (size_t)HSq * Sq;
    const size_t CP5 = (size_t)NF * FP;
    const unsigned FULL = 0xffffffffu;

    int tx = threadIdx.x;
    int c  = 2 * (blockIdx.x * 128 + tx);    // 2 columns per thread
    int ty = blockIdx.y;
    int f  = blockIdx.z;
    int pf  = (f == 0) ? 4 : f - 1;
    int nf2 = (f == 4) ? 0 : f + 1;

    if (ty < NPAIR) {
        int j = 1 + 2 * ty;                  // rows j and j+1
        int lane = tx & 31;
        bool pure = (c >= 2 && c <= Sq - 4);
        bool lo = (lane == 0)  && (c >= 2);       // needs scalar c-1 halo
        bool hi = (lane == 31) && (c <= Sq - 4);  // needs scalar c+2 halo

        // weights for both rows (row j: w**, row j+1: v**) — pure threads only
        const int WP = (HSq - 2) * (Sq - 2);
        float w00, w01, w10, w11, w20, w21, w30, w31, w40, w41, w50, w51;
        float v00, v01, v10, v11, v20, v21, v30, v31, v40, v41, v50, v51;
        if (pure) {
            int kw = (j - 1) * (Sq - 2) + (c - 1);
            int kv = kw + (Sq - 2);
            w00 = wi[kw];          w01 = wi[kw + 1];
            w10 = wi[WP + kw];     w11 = wi[WP + kw + 1];
            w20 = wi[2 * WP + kw]; w21 = wi[2 * WP + kw + 1];
            w30 = wi[3 * WP + kw]; w31 = wi[3 * WP + kw + 1];
            w40 = wi[4 * WP + kw]; w41 = wi[4 * WP + kw + 1];
            w50 = wi[5 * WP + kw]; w51 = wi[5 * WP + kw + 1];
            v00 = wi[kv];          v01 = wi[kv + 1];
            v10 = wi[WP + kv];     v11 = wi[WP + kv + 1];
            v20 = wi[2 * WP + kv]; v21 = wi[2 * WP + kv + 1];
            v30 = wi[3 * WP + kv]; v31 = wi[3 * WP + kv + 1];
            v40 = wi[4 * WP + kv]; v41 = wi[4 * WP + kv + 1];
            v50 = wi[5 * WP + kv]; v51 = wi[5 * WP + kv + 1];
        }

        const float* xp = x + (size_t)f * FP + (size_t)j * Sq;  // row j
        float* ob = out + (size_t)f * FP + (size_t)j * Sq + c;

        #pragma unroll 1
        for (int b = 0; b < Bq; b++) {
            // 4 row vectors (ALL threads — shfl needs full warp participation)
            float2 r0 = *(const float2*)(xp - Sq + c);       // j-1
            float2 r1 = *(const float2*)(xp + c);            // j
            float2 r2 = *(const float2*)(xp + Sq + c);       // j+1
            float2 r3 = *(const float2*)(xp + 2 * Sq + c);   // j+2

            // halo via warp shuffle: lane t-1 holds (.., c-1); lane t+1 holds (c+2, ..)
            float smm = __shfl_up_sync(FULL, r0.y, 1);       // (j-1, c-1)
            float s0  = __shfl_up_sync(FULL, r1.y, 1);       // (j,   c-1)
            float s1  = __shfl_up_sync(FULL, r2.y, 1);       // (j+1, c-1)
            float t1  = __shfl_down_sync(FULL, r1.x, 1);     // (j,   c+2)
            float t2  = __shfl_down_sync(FULL, r2.x, 1);     // (j+1, c+2)
            float t3  = __shfl_down_sync(FULL, r3.x, 1);     // (j+2, c+2)
            if (lo) {
                smm = xp[-Sq + c - 1];
                s0  = xp[c - 1];
                s1  = xp[Sq + c - 1];
            }
            if (hi) {
                t1 = xp[c + 2];
                t2 = xp[Sq + c + 2];
                t3 = xp[2 * Sq + c + 2];
            }

            if (pure) {
                // row j (centers r1.x, r1.y)
                float2 o0 = make_float2((smm  - r1.x) * w00, (r0.x - r1.y) * w01);
                float2 o1 = make_float2((r2.y - r1.x) * w10, (t2   - r1.y) * w11);
                float2 o2 = make_float2((r0.x - r1.x) * w20 + (r1.y - r1.x) * w30,
                                        (r0.y - r1.y) * w21 + (t1   - r1.y) * w31);
                float2 o3 = make_float2((s0   - r1.x) * w40 + (r2.x - r1.x) * w50,
                                        (r1.x - r1.y) * w41 + (r2.y - r1.y) * w51);
                // row j+1 (centers r2.x, r2.y)
                float2 p0 = make_float2((s0   - r2.x) * v00, (r1.x - r2.y) * v01);
                float2 p1 = make_float2((r3.y - r2.x) * v10, (t3   - r2.y) * v11);
                float2 p2 = make_float2((r1.x - r2.x) * v20 + (r2.y - r2.x) * v30,
                                        (r1.y - r2.y) * v21 + (t2   - r2.y) * v31);
                float2 p3 = make_float2((s1   - r2.x) * v40 + (r3.x - r2.x) * v50,
                                        (r2.x - r2.y) * v41 + (r3.y - r2.y) * v51);

                __stcs((float2*)ob,                  o0);
                __stcs((float2*)(ob + CP5),          o1);
                __stcs((float2*)(ob + 2 * CP5),      o2);
                __stcs((float2*)(ob + 3 * CP5),      o3);
                __stcs((float2*)(ob + Sq),           p0);
                __stcs((float2*)(ob + Sq + CP5),     p1);
                __stcs((float2*)(ob + Sq + 2 * CP5), p2);
                __stcs((float2*)(ob + Sq + 3 * CP5), p3);
            } else {
                // edge thread: contains col 0 (c==0) or col S-1 (c==S-2); 2 rows
                const float* xb2 = x + (size_t)b * NF * FP;
                const float* xpf = xb2 + (size_t)f * FP;
                #pragma unroll
                for (int jr = 0; jr < 2; jr++) {
                    int jj = j + jr;
                    float e0[2], e1[2], e2[2], e3[2];
                    #pragma unroll
                    for (int l = 0; l < 2; l++) {
                        int i = c + l;
                        if (i == 0 || i == Sq - 1)
                            bpoint(xb2, poles, we, wcn, wne, wnne, wnw, wnww,
                                   wwe, wsw, wsse, wse, wcs,
                                   b, f, pf, nf2, jj, i, e0[l], e1[l], e2[l], e3[l]);
                        else
                            ipoint(xpf, wi, jj, i, e0[l], e1[l], e2[l], e3[l]);
                    }
                    float* op = ob + (size_t)jr * Sq;
                    __stcs((float2*)op,             make_float2(e0[0], e0[1]));
                    __stcs((float2*)(op + CP5),     make_float2(e1[0], e1[1]));
                    __stcs((float2*)(op + 2 * CP5), make_float2(e2[0], e2[1]));
                    __stcs((float2*)(op + 3 * CP5), make_float2(e3[0], e3[1]));
                }
            }
            xp += NF * FP;
            ob += 20 * FP;
        }
    } else {
        // boundary rows j=0 / j=HS-1: one block-row per (row, b); f from grid
        int q   = ty - NPAIR;                // 0..(2*Bq-1)
        int row = (q < Bq) ? 0 : (HSq - 1);
        int b   = (q < Bq) ? q : q - Bq;
        const float* xb = x + (size_t)b * NF * FP;

        float t0[2], t1[2], t2[2], t3[2];
        #pragma unroll
        for (int l = 0; l < 2; l++) {
            bpoint(xb, poles, we, wcn, wne, wnne, wnw, wnww,
                   wwe, wsw, wsse, wse, wcs,
                   b, f, pf, nf2, row, c + l, t0[l], t1[l], t2[l], t3[l]);
        }
        size_t base = (size_t)(b * 20 + f) * FP + (size_t)row * Sq + c;
        __stcs((float2*)(out + base),           make_float2(t0[0], t0[1]));
        __stcs((float2*)(out + base + CP5),     make_float2(t1[0], t1[1]));
        __stcs((float2*)(out + base + 2 * CP5), make_float2(t2[0], t2[1]));
        __stcs((float2*)(out + base + 3 * CP5), make_float2(t3[0], t3[1]));
    }
}

extern "C" void kernel_launch(void* const* d_in, const int* in_sizes, int n_in,
                              void* d_out, int out_size)
{
    const float* x     = (const float*)d_in[0];
    const float* poles = (const float*)d_in[1];
    const float* wi    = (const float*)d_in[2];
    const float* we    = (const float*)d_in[3];
    const float* wcn   = (const float*)d_in[4];
    const float* wne   = (const float*)d_in[5];
    const float* wnne  = (const float*)d_in[6];
    const float* wnw   = (const float*)d_in[7];
    const float* wnww  = (const float*)d_in[8];
    const float* wwe   = (const float*)d_in[9];
    const float* wsw   = (const float*)d_in[10];
    const float* wsse  = (const float*)d_in[11];
    const float* wse   = (const float*)d_in[12];
    const float* wcs   = (const float*)d_in[13];
    float* out = (float*)d_out;

    // grid.x: 1024/(2*128)=4; grid.y: 255 row-pairs + 8 boundary; grid.z: 5 faces
    dim3 block(128, 1, 1);
    dim3 grid(Sq / (2 * 128), NPAIR + 2 * Bq, NF);
    fused_kernel<<<grid, block>>>(x, poles, wi, we, wcn, wne, wnne, wnw, wnww,
                                  wwe, wsw, wsse, wse, wcs, out);
}

// round 17
// speedup vs baseline: 1.0070x; 1.0070x over previous
#include <cuda_runtime.h>
#include <cuda_bf16.h>
#include <cstdint>

#define Bq 4
#define NF 5
#define HSq 512
#define Sq 1024
#define NPAIR 255   // (HSq-2)/2 row pairs

#define XF(ff,jj,ii) xb[((size_t)(ff)*HSq + (jj))*Sq + (ii)]

// Boundary point: the reference's 12 perimeter cases for one (j,i).
__device__ __forceinline__ void bpoint(
    const float* __restrict__ xb, const float* __restrict__ poles,
    const float* __restrict__ we,   const float* __restrict__ wcn,
    const float* __restrict__ wne,  const float* __restrict__ wnne,
    const float* __restrict__ wnw,  const float* __restrict__ wnww,
    const float* __restrict__ wwe,  const float* __restrict__ wsw,
    const float* __restrict__ wsse, const float* __restrict__ wse,
    const float* __restrict__ wcs,
    int b, int f, int pf, int nf2, int j, int i,
    float& c0, float& c1, float& c2, float& c3)
{
    if (j == 0) {
        float ctr = XF(f, 0, i);
        if (i == 0) {
            c0 = (XF(pf, HSq - 1, HSq - 1) - ctr) * wcs[0];
            c1 = (XF(f, 1, 1) - ctr) * wcs[1];
            c2 = (XF(pf, HSq - 1, HSq) - ctr) * wcs[2] + (XF(f, 0, 1) - ctr) * wcs[3];
            c3 = (XF(f, 1, 0) - ctr) * wcs[4];
        } else if (i <= HSq - 1) {
            int k = i - 1; const int W = HSq - 1;
            c0 = (XF(pf, HSq - 1, HSq + k) - ctr) * we[k];
            c1 = (XF(f, 1, i + 1) - ctr) * we[W + k];
            c2 = (XF(pf, HSq - 1, HSq + 1 + k) - ctr) * we[2 * W + k]
               + (XF(f, 0, i + 1) - ctr) * we[3 * W + k];
            c3 = (XF(f, 0, i - 1) - ctr) * we[4 * W + k]
               + (XF(f, 1, i) - ctr) * we[5 * W + k];
        } else if (i == HSq) {
            c0 = (XF(pf, HSq - 1, Sq - 1) - ctr) * wcn[0];
            c1 = (XF(f, 1, HSq + 1) - ctr) * wcn[1];
            c2 = (XF(f, 0, HSq + 1) - ctr) * wcn[2];
            c3 = (XF(f, 0, HSq - 1) - ctr) * wcn[3] + (XF(f, 1, HSq) - ctr) * wcn[4];
        } else if (i <= Sq - 2) {
            int k = i - (HSq + 1); const int W = HSq - 2;
            c0 = (XF(pf, HSq - 2 - k, Sq - 1) - ctr) * wne[k]
               + (XF(pf, HSq - 1 - k, Sq - 1) - ctr) * wne[W + k];
            c1 = (XF(f, 1, i + 1) - ctr) * wne[2 * W + k]
               + (XF(f, 1, i) - ctr) * wne[3 * W + k];
            c2 = (XF(f, 0, i + 1) - ctr) * wne[4 * W + k];
            c3 = (XF(f, 0, i - 1) - ctr) * wne[5 * W + k];
        } else {
            c0 = (XF(pf, 0, Sq - 1) - ctr) * wnne[0] + (XF(pf, 1, Sq - 1) - ctr) * wnne[1];
            c1 = (XF(nf2, 0, Sq - 1) - ctr) * wnne[2] + (XF(f, 1, Sq - 1) - ctr) * wnne[3];
            c2 = (poles[b * 2 + 1] - ctr) * wnne[4];
            c3 = (XF(f, 0, Sq - 2) - ctr) * wnne[5];
        }
    } else if (j == HSq - 1) {
        float ctr = XF(f, HSq - 1, i);
        if (i == 0) {
            c0 = (XF(pf, HSq - 1, 0) - ctr) * wsse[0];
            c1 = (XF(nf2, HSq - 1, 0) - ctr) * wsse[1];
            c2 = (XF(f, HSq - 2, 0) - ctr) * wsse[2] + (XF(f, HSq - 1, 1) - ctr) * wsse[3];
            c3 = (poles[b * 2 + 0] - ctr) * wsse[4];
        } else if (i <= HSq - 1) {
            int k = i - 1; const int W = HSq - 1;
            c0 = (XF(f, HSq - 2, i - 1) - ctr) * wsw[k];
            c1 = (XF(nf2, HSq - 2 - k, 0) - ctr) * wsw[W + k];
            c2 = (XF(f, HSq - 2, i) - ctr) * wsw[2 * W + k]
               + (XF(f, HSq - 1, i + 1) - ctr) * wsw[3 * W + k];
            c3 = (XF(f, HSq - 1, i - 1) - ctr) * wsw[4 * W + k]
               + (XF(nf2, HSq - 1 - k, 0) - ctr) * wsw[5 * W + k];
        } else if (i <= Sq - 2) {
            int k = i - HSq; const int W = HSq - 1;
            c0 = (XF(f, HSq - 2, i - 1) - ctr) * wwe[k];
            c1 = (XF(nf2, 0, 1 + k) - ctr) * wwe[W + k];
            c2 = (XF(f, HSq - 2, i) - ctr) * wwe[2 * W + k]
               + (XF(f, HSq - 1, i + 1) - ctr) * wwe[3 * W + k];
            c3 = (XF(f, HSq - 1, i - 1) - ctr) * wwe[4 * W + k]
               + (XF(nf2, 0, k) - ctr) * wwe[5 * W + k];
        } else {
            c0 = (XF(f, HSq - 2, Sq - 2) - ctr) * wnww[0];
            c1 = (XF(nf2, 0, HSq) - ctr) * wnww[1];
            c2 = (XF(f, HSq - 2, Sq - 1) - ctr) * wnww[2]
               + (XF(nf2, 0, HSq + 1) - ctr) * wnww[3];
            c3 = (XF(f, HSq - 1, Sq - 2) - ctr) * wnww[4]
               + (XF(nf2, 0, HSq - 1) - ctr) * wnww[5];
        }
    } else if (i == 0) {
        int k = j - 1; const int W = HSq - 2;
        float ctr = XF(f, j, 0);
        c0 = (XF(pf, HSq - 1, HSq - 1 - k) - ctr) * wse[k]
           + (XF(pf, HSq - 1, HSq - 2 - k) - ctr) * wse[W + k];
        c1 = (XF(f, j, 1) - ctr) * wse[2 * W + k]
           + (XF(f, j + 1, 1) - ctr) * wse[3 * W + k];
        c2 = (XF(f, j - 1, 0) - ctr) * wse[4 * W + k];
        c3 = (XF(f, j + 1, 0) - ctr) * wse[5 * W + k];
    } else {
        int k = j - 1; const int W = HSq - 2;
        float ctr = XF(f, j, Sq - 1);
        c0 = (XF(f, j - 1, Sq - 2) - ctr) * wnw[k];
        c1 = (XF(nf2, 0, Sq - 2 - k) - ctr) * wnw[W + k];
        c2 = (XF(f, j - 1, Sq - 1) - ctr) * wnw[2 * W + k]
           + (XF(nf2, 0, Sq - 1 - k) - ctr) * wnw[3 * W + k];
        c3 = (XF(f, j, Sq - 2) - ctr) * wnw[4 * W + k]
           + (XF(f, j + 1, Sq - 1) - ctr) * wnw[5 * W + k];
    }
}

// Inner scalar point (global-memory path, edge threads only)
__device__ __forceinline__ void ipoint(
    const float* __restrict__ xp, const float* __restrict__ wi,
    int j, int i, float& c0, float& c1, float& c2, float& c3)
{
    const int WP = (HSq - 2) * (Sq - 2);
    int k = (j - 1) * (Sq - 2) + (i - 1);
    float ctr = xp[(size_t)j * Sq + i];
    c0 = (xp[(size_t)(j - 1) * Sq + i - 1] - ctr) * wi[k];
    c1 = (xp[(size_t)(j + 1) * Sq + i + 1] - ctr) * wi[WP + k];
    c2 = (xp[(size_t)(j - 1) * Sq + i] - ctr) * wi[2 * WP + k]
       + (xp[(size_t)j * Sq + i + 1] - ctr) * wi[3 * WP + k];
    c3 = (xp[(size_t)j * Sq + i - 1] - ctr) * wi[4 * WP + k]
       + (xp[(size_t)(j + 1) * Sq + i] - ctr) * wi[5 * WP + k];
}

__global__ void __launch_bounds__(128) fused_kernel(
    const float* __restrict__ x,
    const float* __restrict__ poles,
    const float* __restrict__ wi,
    const float* __restrict__ we,   const float* __restrict__ wcn,
    const float* __restrict__ wne,  const float* __restrict__ wnne,
    const float* __restrict__ wnw,  const float* __restrict__ wnww,
    const float* __restrict__ wwe,  const float* __restrict__ wsw,
    const float* __restrict__ wsse, const float* __restrict__ wse,
    const float* __restrict__ wcs,
    float* __restrict__ out)
{
    const size_t FP  = (size_t)HSq * Sq;
    const size_t CP5 = (size_t)NF * FP;
    const unsigned FULL = 0xffffffffu;

    int tx = threadIdx.x;
    int c  = 2 * (blockIdx.x * 128 + tx);    // 2 columns per thread
    int ty = blockIdx.y;
    int f  = blockIdx.z;
    int pf  = (f == 0) ? 4 : f - 1;
    int nf2 = (f == 4) ? 0 : f + 1;

    if (ty < NPAIR) {
        int j = 1 + 2 * ty;                  // rows j and j+1
        int lane = tx & 31;
        bool pure = (c >= 2 && c <= Sq - 4);
        bool lo = (lane == 0)  && (c >= 2);       // needs scalar c-1 halo
        bool hi = (lane == 31) && (c <= Sq - 4);  // needs scalar c+2 halo

        // weights for both rows (row j: w**, row j+1: v**) — pure threads only
        const int WP = (HSq - 2) * (Sq - 2);
        float w00, w01, w10, w11, w20, w21, w30, w31, w40, w41, w50, w51;
        float v00, v01, v10, v11, v20, v21, v30, v31, v40, v41, v50, v51;
        if (pure) {
            int kw = (j - 1) * (Sq - 2) + (c - 1);
            int kv = kw + (Sq - 2);
            w00 = wi[kw];          w01 = wi[kw + 1];
            w10 = wi[WP + kw];     w11 = wi[WP + kw + 1];
            w20 = wi[2 * WP + kw]; w21 = wi[2 * WP + kw + 1];
            w30 = wi[3 * WP + kw]; w31 = wi[3 * WP + kw + 1];
            w40 = wi[4 * WP + kw]; w41 = wi[4 * WP + kw + 1];
            w50 = wi[5 * WP + kw]; w51 = wi[5 * WP + kw + 1];
            v00 = wi[kv];          v01 = wi[kv + 1];
            v10 = wi[WP + kv];     v11 = wi[WP + kv + 1];
            v20 = wi[2 * WP + kv]; v21 = wi[2 * WP + kv + 1];
            v30 = wi[3 * WP + kv]; v31 = wi[3 * WP + kv + 1];
            v40 = wi[4 * WP + kv]; v41 = wi[4 * WP + kv + 1];
            v50 = wi[5 * WP + kv]; v51 = wi[5 * WP + kv + 1];
        }

        const float* xp = x + (size_t)f * FP + (size_t)j * Sq;  // row j
        float* ob = out + (size_t)f * FP + (size_t)j * Sq + c;

        #pragma unroll 1
        for (int b = 0; b < Bq; b++) {
            // 4 row vectors (ALL threads — shfl needs full warp participation)
            float2 r0 = *(const float2*)(xp - Sq + c);       // j-1
            float2 r1 = *(const float2*)(xp + c);            // j
            float2 r2 = *(const float2*)(xp + Sq + c);       // j+1
            float2 r3 = *(const float2*)(xp + 2 * Sq + c);   // j+2

            // halo via warp shuffle: lane t-1 holds (.., c-1); lane t+1 holds (c+2, ..)
            float smm = __shfl_up_sync(FULL, r0.y, 1);       // (j-1, c-1)
            float s0  = __shfl_up_sync(FULL, r1.y, 1);       // (j,   c-1)
            float s1  = __shfl_up_sync(FULL, r2.y, 1);       // (j+1, c-1)
            float t1  = __shfl_down_sync(FULL, r1.x, 1);     // (j,   c+2)
            float t2  = __shfl_down_sync(FULL, r2.x, 1);     // (j+1, c+2)
            float t3  = __shfl_down_sync(FULL, r3.x, 1);     // (j+2, c+2)
            if (lo) {
                smm = xp[-Sq + c - 1];
                s0  = xp[c - 1];
                s1  = xp[Sq + c - 1];
            }
            if (hi) {
                t1 = xp[c + 2];
                t2 = xp[Sq + c + 2];
                t3 = xp[2 * Sq + c + 2];
            }

            if (pure) {
                // row j (centers r1.x, r1.y)
                float2 o0 = make_float2((smm  - r1.x) * w00, (r0.x - r1.y) * w01);
                float2 o1 = make_float2((r2.y - r1.x) * w10, (t2   - r1.y) * w11);
                float2 o2 = make_float2((r0.x - r1.x) * w20 + (r1.y - r1.x) * w30,
                                        (r0.y - r1.y) * w21 + (t1   - r1.y) * w31);
                float2 o3 = make_float2((s0   - r1.x) * w40 + (r2.x - r1.x) * w50,
                                        (r1.x - r1.y) * w41 + (r2.y - r1.y) * w51);
                // row j+1 (centers r2.x, r2.y)
                float2 p0 = make_float2((s0   - r2.x) * v00, (r1.x - r2.y) * v01);
                float2 p1 = make_float2((r3.y - r2.x) * v10, (t3   - r2.y) * v11);
                float2 p2 = make_float2((r1.x - r2.x) * v20 + (r2.y - r2.x) * v30,
                                        (r1.y - r2.y) * v21 + (t2   - r2.y) * v31);
                float2 p3 = make_float2((s1   - r2.x) * v40 + (r3.x - r2.x) * v50,
                                        (r2.x - r2.y) * v41 + (r3.y - r2.y) * v51);

                __stcs((float2*)ob,                  o0);
                __stcs((float2*)(ob + CP5),          o1);
                __stcs((float2*)(ob + 2 * CP5),      o2);
                __stcs((float2*)(ob + 3 * CP5),      o3);
                __stcs((float2*)(ob + Sq),           p0);
                __stcs((float2*)(ob + Sq + CP5),     p1);
                __stcs((float2*)(ob + Sq + 2 * CP5), p2);
                __stcs((float2*)(ob + Sq + 3 * CP5), p3);
            } else {
                // edge thread: contains col 0 (c==0) or col S-1 (c==S-2); 2 rows
                const float* xb2 = x + (size_t)b * NF * FP;
                const float* xpf = xb2 + (size_t)f * FP;
                #pragma unroll
                for (int jr = 0; jr < 2; jr++) {
                    int jj = j + jr;
                    float e0[2], e1[2], e2[2], e3[2];
                    #pragma unroll
                    for (int l = 0; l < 2; l++) {
                        int i = c + l;
                        if (i == 0 || i == Sq - 1)
                            bpoint(xb2, poles, we, wcn, wne, wnne, wnw, wnww,
                                   wwe, wsw, wsse, wse, wcs,
                                   b, f, pf, nf2, jj, i, e0[l], e1[l], e2[l], e3[l]);
                        else
                            ipoint(xpf, wi, jj, i, e0[l], e1[l], e2[l], e3[l]);
                    }
                    float* op = ob + (size_t)jr * Sq;
                    __stcs((float2*)op,             make_float2(e0[0], e0[1]));
                    __stcs((float2*)(op + CP5),     make_float2(e1[0], e1[1]));
                    __stcs((float2*)(op + 2 * CP5), make_float2(e2[0], e2[1]));
                    __stcs((float2*)(op + 3 * CP5), make_float2(e3[0], e3[1]));
                }
            }
            xp += NF * FP;
            ob += 20 * FP;
        }
    } else {
        // boundary rows j=0 / j=HS-1: one block-row per (row, b); f from grid
        int q   = ty - NPAIR;                // 0..(2*Bq-1)
        int row = (q < Bq) ? 0 : (HSq - 1);
        int b   = (q < Bq) ? q : q - Bq;
        const float* xb = x + (size_t)b * NF * FP;

        float t0[2], t1[2], t2[2], t3[2];
        #pragma unroll
        for (int l = 0; l < 2; l++) {
            bpoint(xb, poles, we, wcn, wne, wnne, wnw, wnww,
                   wwe, wsw, wsse, wse, wcs,
                   b, f, pf, nf2, row, c + l, t0[l], t1[l], t2[l], t3[l]);
        }
        size_t base = (size_t)(b * 20 + f) * FP + (size_t)row * Sq + c;
        __stcs((float2*)(out + base),           make_float2(t0[0], t0[1]));
        __stcs((float2*)(out + base + CP5),     make_float2(t1[0], t1[1]));
        __stcs((float2*)(out + base + 2 * CP5), make_float2(t2[0], t2[1]));
        __stcs((float2*)(out + base + 3 * CP5), make_float2(t3[0], t3[1]));
    }
}

extern "C" void kernel_launch(void* const* d_in, const int* in_sizes, int n_in,
                              void* d_out, int out_size)
{
    const float* x     = (const float*)d_in[0];
    const float* poles = (const float*)d_in[1];
    const float* wi    = (const float*)d_in[2];
    const float* we    = (const float*)d_in[3];
    const float* wcn   = (const float*)d_in[4];
    const float* wne   = (const float*)d_in[5];
    const float* wnne  = (const float*)d_in[6];
    const float* wnw   = (const float*)d_in[7];
    const float* wnww  = (const float*)d_in[8];
    const float* wwe   = (const float*)d_in[9];
    const float* wsw   = (const float*)d_in[10];
    const float* wsse  = (const float*)d_in[11];
    const float* wse   = (const float*)d_in[12];
    const float* wcs   = (const float*)d_in[13];
    float* out = (float*)d_out;

    // grid.x: 1024/(2*128)=4; grid.y: 255 row-pairs + 8 boundary; grid.z: 5 faces
    dim3 block(128, 1, 1);
    dim3 grid(Sq / (2 * 128), NPAIR + 2 * Bq, NF);
    fused_kernel<<<grid, block>>>(x, poles, wi, we, wcn, wne, wnne, wnw, wnww,
                                  wwe, wsw, wsse, wse, wcs, out);
}